// round 3
// baseline (speedup 1.0000x reference)
#include <cuda_runtime.h>
#include <math.h>

// Problem constants
#define MTOK   32768      // B*S = 4*8192 tokens
#define DDIM   2048       // embedding dim
#define NEXP   64         // experts
#define TOPK   8
#define NCOLS  128        // router experts (64) || noise experts (64)

// Tiling
#define BM      64        // tokens per CTA
#define DK      32        // k-chunk
#define NTHREADS 128      // 16 token-groups (4 tokens each) x 8 col-groups (16 cols each)
#define LSTRIDE 133       // logits smem row stride (odd, coprime with 32 banks)

__global__ __launch_bounds__(NTHREADS) void router_kernel(
    const float* __restrict__ x,     const float* __restrict__ eps,
    const float* __restrict__ wr,    const float* __restrict__ br,
    const float* __restrict__ wn,    const float* __restrict__ bn,
    const float* __restrict__ wskip, const float* __restrict__ bskip,
    float* __restrict__ out_router, float* __restrict__ out_idx,
    float* __restrict__ out_skip)
{
    __shared__ float xs[DK][BM];        // x tile transposed: xs[d][token]
    __shared__ float ws[DK][NCOLS];     // weight panel: col<64 -> router, else noise
    __shared__ float wss[DK];           // skip weight chunk
    __shared__ float ls[BM][LSTRIDE];   // epilogue logits: [tok][0:64]=router,[64:128]=noise,[128]=skip

    const int tid = threadIdx.x;
    const int tx  = tid & 7;    // col group: cols {4*tx + 32*j + c}
    const int ty  = tid >> 3;   // token group: tokens ty*4 .. ty*4+3
    const int m0  = blockIdx.x * BM;

    float acc[4][16];
    float accs[4] = {0.f, 0.f, 0.f, 0.f};
    #pragma unroll
    for (int t = 0; t < 4; t++)
        #pragma unroll
        for (int c = 0; c < 16; c++) acc[t][c] = 0.f;

    for (int kb = 0; kb < DDIM / DK; kb++) {
        // ---- load x tile (64 tokens x 32 d), store transposed ----
        #pragma unroll
        for (int i = 0; i < 4; i++) {
            int fid = tid + i * NTHREADS;          // 0..511 float4s
            int tok = fid >> 3;
            int dq  = fid & 7;
            float4 v = *(const float4*)(x + (size_t)(m0 + tok) * DDIM + kb * DK + dq * 4);
            xs[dq * 4 + 0][tok] = v.x;
            xs[dq * 4 + 1][tok] = v.y;
            xs[dq * 4 + 2][tok] = v.z;
            xs[dq * 4 + 3][tok] = v.w;
        }
        // ---- load weight panel (32 d x 128 cols = 1024 float4s, 32 float4/row) ----
        #pragma unroll
        for (int i = 0; i < 8; i++) {
            int fid = tid + i * NTHREADS;          // 0..1023 float4s
            int d   = fid >> 5;                    // 0..31
            int col = (fid & 31) * 4;              // 0..124
            const float* src = (col < 64) ? (wr + (size_t)(kb * DK + d) * NEXP + col)
                                          : (wn + (size_t)(kb * DK + d) * NEXP + (col - 64));
            *(float4*)&ws[d][col] = *(const float4*)src;
        }
        if (tid < DK) wss[tid] = wskip[kb * DK + tid];
        __syncthreads();

        // ---- FMA mainloop: inner accumulators per k-chunk (shorter rounding chains) ----
        float inner[4][16];
        float inners[4] = {0.f, 0.f, 0.f, 0.f};
        #pragma unroll
        for (int t = 0; t < 4; t++)
            #pragma unroll
            for (int c = 0; c < 16; c++) inner[t][c] = 0.f;

        #pragma unroll 8
        for (int d = 0; d < DK; d++) {
            float4 xv4 = *(const float4*)&xs[d][ty * 4];
            float xv[4] = {xv4.x, xv4.y, xv4.z, xv4.w};
            float wv[16];
            #pragma unroll
            for (int j = 0; j < 4; j++) {
                float4 w4 = *(const float4*)&ws[d][4 * tx + 32 * j];
                wv[4 * j + 0] = w4.x; wv[4 * j + 1] = w4.y;
                wv[4 * j + 2] = w4.z; wv[4 * j + 3] = w4.w;
            }
            #pragma unroll
            for (int t = 0; t < 4; t++)
                #pragma unroll
                for (int c = 0; c < 16; c++)
                    inner[t][c] = fmaf(xv[t], wv[c], inner[t][c]);
            if (tx == 0) {
                float w = wss[d];
                #pragma unroll
                for (int t = 0; t < 4; t++) inners[t] = fmaf(xv[t], w, inners[t]);
            }
        }
        #pragma unroll
        for (int t = 0; t < 4; t++) {
            #pragma unroll
            for (int c = 0; c < 16; c++) acc[t][c] = __fadd_rn(acc[t][c], inner[t][c]);
            accs[t] = __fadd_rn(accs[t], inners[t]);
        }
        __syncthreads();
    }

    // ---- add biases, stage logits to smem ----
    #pragma unroll
    for (int t = 0; t < 4; t++) {
        int tok = ty * 4 + t;
        #pragma unroll
        for (int j = 0; j < 4; j++)
            #pragma unroll
            for (int c = 0; c < 4; c++) {
                int col = 4 * tx + 32 * j + c;
                float bias = (col < 64) ? __ldg(br + col) : __ldg(bn + col - 64);
                ls[tok][col] = __fadd_rn(acc[t][4 * j + c], bias);
            }
        if (tx == 0) ls[tok][128] = __fadd_rn(accs[t], __ldg(bskip));
    }
    __syncthreads();

    // ---- per-token epilogue: noisy logits -> top-8 -> softmax -> scatter ----
    if (tid < BM) {
        const int   tok = tid;
        const int   g   = m0 + tok;
        const float* ep = eps + (size_t)g * NEXP;

        // noisy = logits + eps * softplus(noise)
        // softplus computed via double intermediate (near-correctly-rounded fp32 result),
        // combine with UNFUSED mul+add to mirror jax's two-rounding sequence.
        for (int e = 0; e < NEXP; e++) {
            float  lg = ls[tok][e];
            float  no = ls[tok][64 + e];
            double nd = (double)no;
            float  sp = (float)(fmax(nd, 0.0) + log1p(exp(-fabs(nd))));
            ls[tok][e] = __fadd_rn(lg, __fmul_rn(ep[e], sp));
        }

        // stable top-8 (lowest index wins ties, like lax.top_k)
        float vals[TOPK]; int idxs[TOPK];
        for (int k = 0; k < TOPK; k++) {
            float best = -3.402823466e38f; int bi = 0;
            for (int e = 0; e < NEXP; e++) {
                float v = ls[tok][e];
                if (v > best) { best = v; bi = e; }
            }
            vals[k] = best; idxs[k] = bi;
            ls[tok][bi] = -3.402823466e38f;
        }

        // softmax over the 8 selected values
        float mx = vals[0];
        float gsv[TOPK]; float s = 0.f;
        #pragma unroll
        for (int k = 0; k < TOPK; k++) { gsv[k] = expf(vals[k] - mx); s += gsv[k]; }
        float inv = 1.f / s;

        float* ro = out_router + (size_t)g * NEXP;
        for (int e = 0; e < NEXP; e++) ro[e] = 0.f;
        #pragma unroll
        for (int k = 0; k < TOPK; k++) ro[idxs[k]] = gsv[k] * inv;

        float* oi = out_idx + (size_t)g * TOPK;
        #pragma unroll
        for (int k = 0; k < TOPK; k++) oi[k] = (float)idxs[k];

        float z = ls[tok][128];
        out_skip[g] = 1.f / (1.f + expf(-z));
    }
}

extern "C" void kernel_launch(void* const* d_in, const int* in_sizes, int n_in,
                              void* d_out, int out_size)
{
    const float* x     = (const float*)d_in[0];
    const float* eps   = (const float*)d_in[1];
    const float* wr    = (const float*)d_in[2];
    const float* br    = (const float*)d_in[3];
    const float* wn    = (const float*)d_in[4];
    const float* bn    = (const float*)d_in[5];
    const float* wskip = (const float*)d_in[6];
    const float* bskip = (const float*)d_in[7];

    float* out        = (float*)d_out;
    float* out_router = out;                                   // [32768, 64]
    float* out_idx    = out + (size_t)MTOK * NEXP;             // [32768, 8] as float
    float* out_skip   = out_idx + (size_t)MTOK * TOPK;         // [32768, 1]

    router_kernel<<<MTOK / BM, NTHREADS>>>(x, eps, wr, br, wn, bn, wskip, bskip,
                                           out_router, out_idx, out_skip);
}

// round 5
// speedup vs baseline: 1.3959x; 1.3959x over previous
#include <cuda_runtime.h>
#include <math.h>

// Problem constants
#define MTOK   32768      // B*S
#define DDIM   2048
#define NEXP   64
#define TOPK   8
#define NCOLS  128        // router(64) || noise(64)

// Tiling
#define BM      64        // tokens per CTA
#define DK      32        // k-chunk
#define NTHREADS 256      // tx: 16 col-groups (8 cols), ty: 16 token-groups (4 tokens)
#define DKP     (DK + 1)  // xs row pad in float2 units
#define LSTRIDE 133       // epilogue logits row stride (coprime with 32)

// smem union layout (bytes). Mainloop region and epilogue ls region alias.
#define XS_OFF   0                         // float2 xs[BM][DKP]   = 64*33*8  = 16896
#define WS_OFF   16896                     // float  ws[DK][NCOLS] = 32*128*4 = 16384
#define WSS_OFF  (16896 + 16384)           // float2 wss[DK]       = 256
#define SMEM_BYTES 34064                   // >= ls[64][133]*4 = 34048

__device__ __forceinline__ void fma2(unsigned long long &acc, unsigned long long a,
                                     unsigned long long b) {
    asm("fma.rn.f32x2 %0, %1, %2, %0;" : "+l"(acc) : "l"(a), "l"(b));
}
__device__ __forceinline__ void add2(unsigned long long &acc, unsigned long long a) {
    asm("add.rn.f32x2 %0, %0, %1;" : "+l"(acc) : "l"(a));
}
__device__ __forceinline__ float lo2(unsigned long long v) { return __uint_as_float((unsigned)v); }
__device__ __forceinline__ float hi2(unsigned long long v) { return __uint_as_float((unsigned)(v >> 32)); }

__global__ __launch_bounds__(NTHREADS, 2) void router_kernel(
    const float* __restrict__ x,     const float* __restrict__ eps,
    const float* __restrict__ wr,    const float* __restrict__ br,
    const float* __restrict__ wn,    const float* __restrict__ bn,
    const float* __restrict__ wskip, const float* __restrict__ bskip,
    float* __restrict__ out_router, float* __restrict__ out_idx,
    float* __restrict__ out_skip)
{
    __shared__ __align__(16) unsigned char smem[SMEM_BYTES];
    float2 (*xs)[DKP]   = (float2(*)[DKP])(smem + XS_OFF);   // (x,x) duplicated
    float  (*ws)[NCOLS] = (float(*)[NCOLS])(smem + WS_OFF);
    float2 *wss         = (float2*)(smem + WSS_OFF);
    float  (*ls)[LSTRIDE] = (float(*)[LSTRIDE])smem;         // aliases xs/ws (epilogue only)

    const int tid = threadIdx.x;
    const int tx  = tid & 15;    // cols: 4*tx + 64*j + c  (j=0,1; c=0..3)
    const int ty  = tid >> 4;    // tokens ty*4 .. ty*4+3
    const int m0  = blockIdx.x * BM;

    unsigned long long acc[4][4];   // outer accs: [tok][pair]; pair p -> cols 4tx + 64*(p>>1) + 2*(p&1) + {0,1}
    float accs[4] = {0.f, 0.f, 0.f, 0.f};
    #pragma unroll
    for (int t = 0; t < 4; t++)
        #pragma unroll
        for (int p = 0; p < 4; p++) acc[t][p] = 0ull;

    for (int kb = 0; kb < DDIM / DK; kb++) {
        // ---- x tile: 512 float4s over 256 threads x2, stored transposed + duplicated ----
        #pragma unroll
        for (int i = 0; i < 2; i++) {
            int fid = tid + i * NTHREADS;
            int tok = fid >> 3;
            int dq  = fid & 7;
            float4 v = *(const float4*)(x + (size_t)(m0 + tok) * DDIM + kb * DK + dq * 4);
            xs[tok][dq * 4 + 0] = make_float2(v.x, v.x);
            xs[tok][dq * 4 + 1] = make_float2(v.y, v.y);
            xs[tok][dq * 4 + 2] = make_float2(v.z, v.z);
            xs[tok][dq * 4 + 3] = make_float2(v.w, v.w);
        }
        // ---- weight panel: 1024 float4s (32 rows x 32 float4/row) ----
        #pragma unroll
        for (int i = 0; i < 4; i++) {
            int fid = tid + i * NTHREADS;
            int d   = fid >> 5;
            int col = (fid & 31) * 4;
            const float* src = (col < 64) ? (wr + (size_t)(kb * DK + d) * NEXP + col)
                                          : (wn + (size_t)(kb * DK + d) * NEXP + (col - 64));
            *(float4*)&ws[d][col] = *(const float4*)src;
        }
        if (tid < DK) {
            float w = wskip[kb * DK + tid];
            wss[tid] = make_float2(w, w);
        }
        __syncthreads();

        // ---- FFMA2 mainloop (inner accumulators per k-chunk for short rounding chains) ----
        unsigned long long inner[4][4];
        float inners[4] = {0.f, 0.f, 0.f, 0.f};
        #pragma unroll
        for (int t = 0; t < 4; t++)
            #pragma unroll
            for (int p = 0; p < 4; p++) inner[t][p] = 0ull;

        #pragma unroll
        for (int d = 0; d < DK; d++) {
            unsigned long long x2[4];
            #pragma unroll
            for (int t = 0; t < 4; t++)
                x2[t] = *(const unsigned long long*)&xs[ty * 4 + t][d];
            ulonglong2 wA = *(const ulonglong2*)&ws[d][4 * tx];        // cols 4tx+0..3
            ulonglong2 wB = *(const ulonglong2*)&ws[d][4 * tx + 64];   // cols 4tx+64..67
            #pragma unroll
            for (int t = 0; t < 4; t++) {
                fma2(inner[t][0], x2[t], wA.x);
                fma2(inner[t][1], x2[t], wA.y);
                fma2(inner[t][2], x2[t], wB.x);
                fma2(inner[t][3], x2[t], wB.y);
            }
            if (tx == 0) {
                float w = wss[d].x;
                #pragma unroll
                for (int t = 0; t < 4; t++) inners[t] = fmaf(lo2(x2[t]), w, inners[t]);
            }
        }
        #pragma unroll
        for (int t = 0; t < 4; t++) {
            #pragma unroll
            for (int p = 0; p < 4; p++) add2(acc[t][p], inner[t][p]);
            accs[t] = __fadd_rn(accs[t], inners[t]);
        }
        __syncthreads();
    }

    // ---- add biases, stage logits into ls (aliases mainloop smem; all reads done) ----
    #pragma unroll
    for (int t = 0; t < 4; t++) {
        int tok = ty * 4 + t;
        #pragma unroll
        for (int p = 0; p < 4; p++) {
            int c0 = 4 * tx + 64 * (p >> 1) + 2 * (p & 1);
            float b0 = (c0 < 64) ? __ldg(br + c0) : __ldg(bn + c0 - 64);
            float b1 = (c0 + 1 < 64) ? __ldg(br + c0 + 1) : __ldg(bn + c0 + 1 - 64);
            ls[tok][c0]     = __fadd_rn(lo2(acc[t][p]), b0);
            ls[tok][c0 + 1] = __fadd_rn(hi2(acc[t][p]), b1);
        }
        if (tx == 0) ls[tok][128] = __fadd_rn(accs[t], __ldg(bskip));
    }
    __syncthreads();

    // ---- noisy logits: parallel over all 256 threads (4096 (tok,e) pairs) ----
    #pragma unroll
    for (int i = 0; i < 16; i++) {
        int fid = tid + i * NTHREADS;
        int tok = fid >> 6;
        int e   = fid & 63;
        float  lg = ls[tok][e];
        float  no = ls[tok][64 + e];
        double nd = (double)no;
        float  sp = (float)(fmax(nd, 0.0) + log1p(exp(-fabs(nd))));
        float  ev = __ldg(eps + (size_t)(m0 + tok) * NEXP + e);
        ls[tok][e] = __fadd_rn(lg, __fmul_rn(ev, sp));
    }
    __syncthreads();

    // ---- top-8 + softmax (one thread per token), results staged back into ls ----
    if (tid < BM) {
        const int tok = tid;

        float vals[TOPK]; int idxs[TOPK];
        for (int k = 0; k < TOPK; k++) {
            float best = -3.402823466e38f; int bi = 0;
            for (int e = 0; e < NEXP; e++) {
                float v = ls[tok][e];
                if (v > best) { best = v; bi = e; }
            }
            vals[k] = best; idxs[k] = bi;
            ls[tok][bi] = -3.402823466e38f;
        }

        float mx = vals[0];
        float gsv[TOPK]; float s = 0.f;
        #pragma unroll
        for (int k = 0; k < TOPK; k++) { gsv[k] = expf(vals[k] - mx); s += gsv[k]; }
        float inv = 1.f / s;

        for (int e = 0; e < NEXP; e++) ls[tok][e] = 0.f;
        #pragma unroll
        for (int k = 0; k < TOPK; k++) ls[tok][idxs[k]] = gsv[k] * inv;
        #pragma unroll
        for (int k = 0; k < TOPK; k++) ls[tok][64 + k] = (float)idxs[k];
    }
    __syncthreads();

    // ---- cooperative coalesced stores ----
    // router gates: 64x64 floats
    #pragma unroll
    for (int i = 0; i < 16; i++) {
        int fid = tid + i * NTHREADS;      // 0..4095
        int tok = fid >> 6;
        int e   = fid & 63;
        out_router[(size_t)(m0 + tok) * NEXP + e] = ls[tok][e];
    }
    // indices: 64x8 floats
    #pragma unroll
    for (int i = 0; i < 2; i++) {
        int fid = tid + i * NTHREADS;      // 0..511
        int tok = fid >> 3;
        int k   = fid & 7;
        out_idx[(size_t)(m0 + tok) * TOPK + k] = ls[tok][64 + k];
    }
    // skip gate
    if (tid < BM) {
        float z = ls[tid][128];
        out_skip[m0 + tid] = 1.f / (1.f + expf(-z));
    }
}

extern "C" void kernel_launch(void* const* d_in, const int* in_sizes, int n_in,
                              void* d_out, int out_size)
{
    const float* x     = (const float*)d_in[0];
    const float* eps   = (const float*)d_in[1];
    const float* wr    = (const float*)d_in[2];
    const float* br    = (const float*)d_in[3];
    const float* wn    = (const float*)d_in[4];
    const float* bn    = (const float*)d_in[5];
    const float* wskip = (const float*)d_in[6];
    const float* bskip = (const float*)d_in[7];

    float* out        = (float*)d_out;
    float* out_router = out;                                   // [32768, 64]
    float* out_idx    = out + (size_t)MTOK * NEXP;             // [32768, 8] as float
    float* out_skip   = out_idx + (size_t)MTOK * TOPK;         // [32768, 1]

    router_kernel<<<MTOK / BM, NTHREADS>>>(x, eps, wr, br, wn, bn, wskip, bskip,
                                           out_router, out_idx, out_skip);
}